// round 16
// baseline (speedup 1.0000x reference)
#include <cuda_runtime.h>
#include <cuda_bf16.h>
#include <cuda_fp16.h>
#include <math.h>
#include <stdint.h>
#include <float.h>

#define SDIM 1024
#define DDIM 1024
#define NH 16
#define HD 64
#define NBH 64
#define MTOT 4096

// ---------------- scratch (__device__ globals; no runtime alloc) ------------
__device__ float g_qh[NBH * SDIM * HD];
__device__ float g_kh[NBH * SDIM * HD];
__device__ float g_vh[NBH * SDIM * HD];
__device__ float g_attn[(size_t)MTOT * DDIM];
__device__ float g_wqT[DDIM * DDIM];
__device__ float g_wkT[DDIM * DDIM];
__device__ float g_wvT[DDIM * DDIM];
__device__ float g_woT[DDIM * DDIM];
// pre-split fp16 hi/lo, permuted word layout ([row][512 words])
__device__ uint32_t g_Qhi[MTOT * 512], g_Qlo[MTOT * 512];
__device__ uint32_t g_Khi[MTOT * 512], g_Klo[MTOT * 512];
__device__ uint32_t g_Vhi[MTOT * 512], g_Vlo[MTOT * 512];
__device__ uint32_t g_wqhi[DDIM * 512], g_wqlo[DDIM * 512];
__device__ uint32_t g_wkhi[DDIM * 512], g_wklo[DDIM * 512];
__device__ uint32_t g_wvhi[DDIM * 512], g_wvlo[DDIM * 512];

// ---------------- helpers ----------------------------------------------------
#define MMA_BF16(d, a0, a1, a2, a3, b0, b1) \
    asm volatile("mma.sync.aligned.m16n8k16.row.col.f32.bf16.bf16.f32 " \
                 "{%0,%1,%2,%3}, {%4,%5,%6,%7}, {%8,%9}, {%0,%1,%2,%3};" \
                 : "+f"((d)[0]), "+f"((d)[1]), "+f"((d)[2]), "+f"((d)[3]) \
                 : "r"(a0), "r"(a1), "r"(a2), "r"(a3), "r"(b0), "r"(b1))

#define MMA_F16(d, a0, a1, a2, a3, b0, b1) \
    asm volatile("mma.sync.aligned.m16n8k16.row.col.f32.f16.f16.f32 " \
                 "{%0,%1,%2,%3}, {%4,%5,%6,%7}, {%8,%9}, {%0,%1,%2,%3};" \
                 : "+f"((d)[0]), "+f"((d)[1]), "+f"((d)[2]), "+f"((d)[3]) \
                 : "r"(a0), "r"(a1), "r"(a2), "r"(a3), "r"(b0), "r"(b1))

__device__ __forceinline__ unsigned fenc(float f) {
    unsigned u = __float_as_uint(f);
    return (u & 0x80000000u) ? ~u : (u | 0x80000000u);
}
__device__ __forceinline__ float fdec(unsigned u) {
    unsigned v = (u & 0x80000000u) ? (u & 0x7FFFFFFFu) : ~u;
    return __uint_as_float(v);
}
__device__ __forceinline__ uint32_t pack_half(float a, float b) {
    __half2 v = __floats2half2_rn(a, b);
    return *reinterpret_cast<uint32_t*>(&v);
}
__device__ __forceinline__ uint32_t pack_bf16(float a, float b) {
    __nv_bfloat162 v = __floats2bfloat162_rn(a, b);
    return *reinterpret_cast<uint32_t*>(&v);
}

// ---------------------------------------------------------------------------
// Split 6 matrices (Q,K,V: 4096 rows; wqT,wkT,wvT: 1024 rows) into fp16
// hi/lo, permuted word layout: word W = ch*16 + gp*8 + p holds logical floats
// f = ch*32 + gp*16 + 2*j, j = ((p&1)<<2)|(p>>1)  (inverse of the proven
// staging permutation phys(j) = 2*(j&3) + (j>>2)).
// ---------------------------------------------------------------------------
__global__ __launch_bounds__(256)
void split6_kernel(const float* __restrict__ Q,  uint32_t* __restrict__ Qh, uint32_t* __restrict__ Ql,
                   const float* __restrict__ K,  uint32_t* __restrict__ Kh, uint32_t* __restrict__ Kl,
                   const float* __restrict__ V,  uint32_t* __restrict__ Vh, uint32_t* __restrict__ Vl,
                   const float* __restrict__ Wq, uint32_t* __restrict__ Wqh, uint32_t* __restrict__ Wql,
                   const float* __restrict__ Wk, uint32_t* __restrict__ Wkh, uint32_t* __restrict__ Wkl,
                   const float* __restrict__ Wv, uint32_t* __restrict__ Wvh, uint32_t* __restrict__ Wvl)
{
    const int z = blockIdx.y;
    const int nrows = (z < 3) ? MTOT : DDIM;
    const int rb = blockIdx.x;
    if (rb * 128 >= nrows) return;

    const float* X  = (z == 0) ? Q  : (z == 1) ? K  : (z == 2) ? V
                    : (z == 3) ? Wq : (z == 4) ? Wk : Wv;
    uint32_t* Xh    = (z == 0) ? Qh : (z == 1) ? Kh : (z == 2) ? Vh
                    : (z == 3) ? Wqh : (z == 4) ? Wkh : Wvh;
    uint32_t* Xl    = (z == 0) ? Ql : (z == 1) ? Kl : (z == 2) ? Vl
                    : (z == 3) ? Wql : (z == 4) ? Wkl : Wvl;

    for (int it = threadIdx.x; it < 128 * 512; it += 256) {
        int r = rb * 128 + (it >> 9);
        int W = it & 511;
        int ch = W >> 4, p16 = W & 15;
        int gp = p16 >> 3, p = p16 & 7;
        int j = ((p & 1) << 2) | (p >> 1);
        int f = ch * 32 + gp * 16 + j * 2;
        float x0 = X[(size_t)r * 1024 + f];
        float x1 = X[(size_t)r * 1024 + f + 1];
        float h0 = __half2float(__float2half_rn(x0));
        float h1 = __half2float(__float2half_rn(x1));
        Xh[(size_t)r * 512 + W] = pack_half(h0, h1);
        Xl[(size_t)r * 512 + W] = pack_half(x0 - h0, x1 - h1);
    }
}

// ---------------------------------------------------------------------------
// Pre-split fp16 3-product GEMM: Q,K,V projections in one launch (z=3),
// head_layout output. Staging = pure uint4 copies (zero conversion ALU);
// frag loads / mma / epilogue byte-identical to the R13-proven f16 kernel.
// ---------------------------------------------------------------------------
#define BPLD 20
#define BPLANE (128 * BPLD)
#define GB_SMEM (2 * 4 * BPLANE * 4)   // 81920 B

__global__ __launch_bounds__(256, 1)
void mma_gemm_f16pre(const uint32_t* __restrict__ A0h, const uint32_t* __restrict__ A0l,
                     const uint32_t* __restrict__ B0h, const uint32_t* __restrict__ B0l,
                     const uint32_t* __restrict__ A1h, const uint32_t* __restrict__ A1l,
                     const uint32_t* __restrict__ B1h, const uint32_t* __restrict__ B1l,
                     const uint32_t* __restrict__ A2h, const uint32_t* __restrict__ A2l,
                     const uint32_t* __restrict__ B2h, const uint32_t* __restrict__ B2l,
                     const float* __restrict__ b0, const float* __restrict__ b1,
                     const float* __restrict__ b2,
                     float* __restrict__ C0, float* __restrict__ C1,
                     float* __restrict__ C2)
{
    extern __shared__ __align__(16) uint32_t smu[];
    const int z = blockIdx.z;
    const uint32_t* Agh = (z == 0) ? A0h : (z == 1) ? A1h : A2h;
    const uint32_t* Agl = (z == 0) ? A0l : (z == 1) ? A1l : A2l;
    const uint32_t* Bgh = (z == 0) ? B0h : (z == 1) ? B1h : B2h;
    const uint32_t* Bgl = (z == 0) ? B0l : (z == 1) ? B1l : B2l;
    const float* bias   = (z == 0) ? b0  : (z == 1) ? b1  : b2;
    float* C            = (z == 0) ? C0  : (z == 1) ? C1  : C2;

    const int tid = threadIdx.x;
    const int w = tid >> 5;
    const int lane = tid & 31;
    const int g = lane >> 2;
    const int t = lane & 3;
    const int m0 = (w & 1) << 6;
    const int n0 = (w >> 1) << 5;
    const int row0 = blockIdx.y << 7;
    const int col0 = blockIdx.x << 7;

    float d[4][4][4];
#pragma unroll
    for (int i = 0; i < 4; i++)
#pragma unroll
        for (int j = 0; j < 4; j++)
#pragma unroll
            for (int e = 0; e < 4; e++) d[i][j][e] = 0.f;

    // staging slot: idx = i*256+tid (i<2); r = idx>>2, q4 = (idx&3)*4
    const int r_s  = tid >> 2;          // with i offset: +64 rows
    const int q4_s = (tid & 3) << 2;

    uint4 pah[2], pal[2], pbh[2], pbl[2];
#pragma unroll
    for (int i = 0; i < 2; i++) {
        int r = r_s + i * 64;
        size_t ga = (size_t)(row0 + r) * 512 + q4_s;
        size_t gb = (size_t)(col0 + r) * 512 + q4_s;
        pah[i] = *(const uint4*)&Agh[ga];
        pal[i] = *(const uint4*)&Agl[ga];
        pbh[i] = *(const uint4*)&Bgh[gb];
        pbl[i] = *(const uint4*)&Bgl[gb];
    }

    for (int ch = 0; ch < 32; ch++) {
        const int sb = ch & 1;
        uint32_t* Ah  = smu + sb * 4 * BPLANE;
        uint32_t* Al  = Ah + BPLANE;
        uint32_t* Bh_ = Ah + 2 * BPLANE;
        uint32_t* Bl  = Ah + 3 * BPLANE;

#pragma unroll
        for (int i = 0; i < 2; i++) {
            int r = r_s + i * 64;
            int so = r * BPLD + q4_s;
            *(uint4*)&Ah[so]  = pah[i];
            *(uint4*)&Al[so]  = pal[i];
            *(uint4*)&Bh_[so] = pbh[i];
            *(uint4*)&Bl[so]  = pbl[i];
        }
        __syncthreads();

        if (ch < 31) {
            const int wc = (ch + 1) << 4;
#pragma unroll
            for (int i = 0; i < 2; i++) {
                int r = r_s + i * 64;
                size_t ga = (size_t)(row0 + r) * 512 + wc + q4_s;
                size_t gb = (size_t)(col0 + r) * 512 + wc + q4_s;
                pah[i] = *(const uint4*)&Agh[ga];
                pal[i] = *(const uint4*)&Agl[ga];
                pbh[i] = *(const uint4*)&Bgh[gb];
                pbl[i] = *(const uint4*)&Bgl[gb];
            }
        }

#pragma unroll
        for (int ks = 0; ks < 2; ks++) {
            const int kw = (ks << 3) + (t << 1);
            uint2 aH[4][2], aL[4][2], bH[4], bL[4];
#pragma unroll
            for (int mt = 0; mt < 4; mt++) {
                int rw = (m0 + (mt << 4) + g) * BPLD + kw;
                aH[mt][0] = *(const uint2*)&Ah[rw];
                aH[mt][1] = *(const uint2*)&Ah[rw + 8 * BPLD];
                aL[mt][0] = *(const uint2*)&Al[rw];
                aL[mt][1] = *(const uint2*)&Al[rw + 8 * BPLD];
            }
#pragma unroll
            for (int nt = 0; nt < 4; nt++) {
                int rw = (n0 + (nt << 3) + g) * BPLD + kw;
                bH[nt] = *(const uint2*)&Bh_[rw];
                bL[nt] = *(const uint2*)&Bl[rw];
            }
#pragma unroll
            for (int mt = 0; mt < 4; mt++)
#pragma unroll
                for (int nt = 0; nt < 4; nt++) {
                    MMA_F16(d[mt][nt], aH[mt][0].x, aH[mt][1].x, aH[mt][0].y, aH[mt][1].y,
                            bH[nt].x, bH[nt].y);
                    MMA_F16(d[mt][nt], aH[mt][0].x, aH[mt][1].x, aH[mt][0].y, aH[mt][1].y,
                            bL[nt].x, bL[nt].y);
                    MMA_F16(d[mt][nt], aL[mt][0].x, aL[mt][1].x, aL[mt][0].y, aL[mt][1].y,
                            bH[nt].x, bH[nt].y);
                }
        }
        __syncthreads();   // reads done before next store into same buffer's pair
    }

#pragma unroll
    for (int mt = 0; mt < 4; mt++) {
#pragma unroll
        for (int nt = 0; nt < 4; nt++) {
            int c = col0 + n0 + (nt << 3) + (t << 1);
            float b0v = bias[c];
            float b1v = bias[c + 1];
#pragma unroll
            for (int half = 0; half < 2; half++) {
                int r = row0 + m0 + (mt << 4) + g + half * 8;
                float2 v;
                v.x = d[mt][nt][half * 2 + 0] + b0v;
                v.y = d[mt][nt][half * 2 + 1] + b1v;
                int b_ = r >> 10, s2 = r & 1023;
                int h_ = c >> 6, d_ = c & 63;
                *(float2*)(C + (((size_t)(b_ * NH + h_) * SDIM + s2) << 6) + d_) = v;
            }
        }
    }
}

// ---------------------------------------------------------------------------
// FUSED scores + mask + sparse AV — R15 PROVEN VERSION, FROZEN.
// ---------------------------------------------------------------------------
#define QLD 36
#define CAP 32
#define F_SMEM (18432 + 18432 + 512 + 512 + 16384 + 16384)   // 70656 B

__global__ __launch_bounds__(256, 2)
void fused_scores_mask(const float* __restrict__ qh, const float* __restrict__ kh,
                       const float* __restrict__ vh, float* __restrict__ attn)
{
    extern __shared__ __align__(16) char fsm[];
    uint32_t* Ap      = (uint32_t*)fsm;
    uint32_t* Bp      = (uint32_t*)(fsm + 18432);
    unsigned* rowmaxU = (unsigned*)(fsm + 36864);
    int*      cntI    = (int*)(fsm + 37376);
    int*      listKs  = (int*)(fsm + 37888);
    float*    listSs  = (float*)(fsm + 54272);

    const int tid = threadIdx.x;
    const int w = tid >> 5;
    const int lane = tid & 31;
    const int g = lane >> 2;
    const int t = lane & 3;
    const int m0 = (w & 1) << 6;
    const int n0 = (w >> 1) << 5;
    const int bh = blockIdx.y;
    const int q0 = blockIdx.x << 7;

    const float* qbase = qh + ((size_t)bh * SDIM + q0) * HD;
    const float* kbh   = kh + (size_t)bh * SDIM * HD;
    const float* vb    = vh + (size_t)bh * SDIM * HD;

    if (tid < 128) { rowmaxU[tid] = 0u; cntI[tid] = 0; }

#pragma unroll
    for (int i = 0; i < 8; i++) {
        int idx = i * 256 + tid;
        int r = idx >> 4, s16 = idx & 15;
        float4 v = *(const float4*)(qbase + (size_t)r * HD + s16 * 4);
        int j0 = (2 * s16) & 7;
        int wo = r * QLD + ((s16 >> 2) << 3) + ((j0 & 3) << 1) + (j0 >> 2);
        Ap[wo]     = pack_half(v.x, v.y);
        Ap[wo + 2] = pack_half(v.z, v.w);
    }

    for (int ch = 0; ch < 8; ch++) {
        __syncthreads();
#pragma unroll
        for (int i = 0; i < 8; i++) {
            int idx = i * 256 + tid;
            int r = idx >> 4, s16 = idx & 15;
            float4 v = *(const float4*)(kbh + (size_t)(ch * 128 + r) * HD + s16 * 4);
            int j0 = (2 * s16) & 7;
            int wo = r * QLD + ((s16 >> 2) << 3) + ((j0 & 3) << 1) + (j0 >> 2);
            Bp[wo]     = pack_half(v.x, v.y);
            Bp[wo + 2] = pack_half(v.z, v.w);
        }
        __syncthreads();

        float d[4][4][4];
#pragma unroll
        for (int i = 0; i < 4; i++)
#pragma unroll
            for (int j = 0; j < 4; j++)
#pragma unroll
                for (int e = 0; e < 4; e++) d[i][j][e] = 0.f;

#pragma unroll
        for (int ks = 0; ks < 4; ks++) {
            const int kw = (ks << 3) + (t << 1);
            uint2 aF[4][2], bF[4];
#pragma unroll
            for (int mt = 0; mt < 4; mt++) {
                int rw = (m0 + (mt << 4) + g) * QLD + kw;
                aF[mt][0] = *(const uint2*)&Ap[rw];
                aF[mt][1] = *(const uint2*)&Ap[rw + 8 * QLD];
            }
#pragma unroll
            for (int nt = 0; nt < 4; nt++) {
                int rw = (n0 + (nt << 3) + g) * QLD + kw;
                bF[nt] = *(const uint2*)&Bp[rw];
            }
#pragma unroll
            for (int mt = 0; mt < 4; mt++)
#pragma unroll
                for (int nt = 0; nt < 4; nt++)
                    MMA_F16(d[mt][nt], aF[mt][0].x, aF[mt][1].x,
                            aF[mt][0].y, aF[mt][1].y, bF[nt].x, bF[nt].y);
        }

#pragma unroll
        for (int mt = 0; mt < 4; mt++)
#pragma unroll
            for (int half = 0; half < 2; half++) {
                float mx = -FLT_MAX;
#pragma unroll
                for (int nt = 0; nt < 4; nt++)
                    mx = fmaxf(mx, fmaxf(d[mt][nt][half * 2],
                                         d[mt][nt][half * 2 + 1]));
                mx = fmaxf(mx, __shfl_xor_sync(0xffffffffu, mx, 1));
                mx = fmaxf(mx, __shfl_xor_sync(0xffffffffu, mx, 2));
                if (t == 0)
                    atomicMax(&rowmaxU[m0 + (mt << 4) + g + half * 8], fenc(mx));
            }
        __syncthreads();

#pragma unroll
        for (int mt = 0; mt < 4; mt++)
#pragma unroll
            for (int half = 0; half < 2; half++) {
                const int row = m0 + (mt << 4) + g + half * 8;
                const float band = fdec(rowmaxU[row]) - 0.32f;
#pragma unroll
                for (int nt = 0; nt < 4; nt++)
#pragma unroll
                    for (int e = 0; e < 2; e++) {
                        float v = d[mt][nt][half * 2 + e];
                        if (v >= band) {
                            int pos = atomicAdd(&cntI[row], 1);
                            if (pos < CAP) {
                                listKs[row * CAP + pos] =
                                    ch * 128 + n0 + (nt << 3) + (t << 1) + e;
                                listSs[row * CAP + pos] = v;
                            }
                        }
                    }
            }
    }
    __syncthreads();

    float* fb = (float*)fsm;

    for (int rr = 0; rr < 16; rr++) {
        const int r = w * 16 + rr;
        const int q = q0 + r;
        const float* qrow = qbase + (size_t)r * HD;
        int cnt = cntI[r];
        float a0 = 0.f, a1 = 0.f;

        if (cnt <= CAP) {
            if (lane == 0) {
                const float bandf = fdec(rowmaxU[r]) - 0.32f;
                int nc = 0;
                for (int j = 0; j < cnt; j++) {
                    if (listSs[r * CAP + j] >= bandf)
                        listKs[r * CAP + nc++] = listKs[r * CAP + j];
                }
                for (int a = 1; a < nc; a++) {
                    int key = listKs[r * CAP + a];
                    int b = a - 1;
                    while (b >= 0 && listKs[r * CAP + b] > key) {
                        listKs[r * CAP + b + 1] = listKs[r * CAP + b];
                        b--;
                    }
                    listKs[r * CAP + b + 1] = key;
                }
                cntI[r] = nc;
            }
            __syncwarp();
            cnt = cntI[r];

            const float qa = qrow[lane], qb = qrow[lane + 32];
            for (int j = 0; j < cnt; j++) {
                const int k = listKs[r * CAP + j];
                const float* krow = kbh + (size_t)k * HD;
                float p = qa * krow[lane] + qb * krow[lane + 32];
#pragma unroll
                for (int o = 16; o > 0; o >>= 1)
                    p += __shfl_xor_sync(0xffffffffu, p, o);
                if (lane == 0) listSs[r * CAP + j] = p * 0.125f;
            }
            __syncwarp();

            float m_ex = -FLT_MAX;
            for (int j = 0; j < cnt; j++) m_ex = fmaxf(m_ex, listSs[r * CAP + j]);
            const float xm = m_ex / 0.001f;
            float Z = 0.f;
            for (int j = 0; j < cnt; j++)
                Z += expf(listSs[r * CAP + j] / 0.001f - xm);

            float m2 = -FLT_MAX;
            for (int j = 0; j < cnt; j++) {
                float att = expf(listSs[r * CAP + j] / 0.001f - xm) / Z;
                if (att >= 0.019f) m2 = fmaxf(m2, listSs[r * CAP + j]);
            }
            float wsum = 0.f;
            for (int j = 0; j < cnt; j++) {
                float s = listSs[r * CAP + j];
                float att = expf(s / 0.001f - xm) / Z;
                if (att >= 0.019f) wsum += expf(s - m2);
            }
            for (int j = 0; j < cnt; j++) {
                float s = listSs[r * CAP + j];
                float att = expf(s / 0.001f - xm) / Z;
                if (att >= 0.019f) {
                    float wgt = expf(s - m2) / wsum;
                    const int k = listKs[r * CAP + j];
                    a0 += wgt * vb[(size_t)k * HD + lane];
                    a1 += wgt * vb[(size_t)k * HD + lane + 32];
                }
            }
        } else {
            float* frow = fb + w * 1024;
            for (int it = 0; it < 32; it++) {
                int k = it * 32 + lane;
                const float* krow = kbh + (size_t)k * HD;
                float p = 0.f;
#pragma unroll
                for (int dd = 0; dd < 64; dd++) p += qrow[dd] * krow[dd];
                frow[k] = p * 0.125f;
            }
            __syncwarp();
            float me = -FLT_MAX;
            for (int k = lane; k < 1024; k += 32) me = fmaxf(me, frow[k]);
#pragma unroll
            for (int o = 16; o > 0; o >>= 1)
                me = fmaxf(me, __shfl_xor_sync(0xffffffffu, me, o));
            const float xm = me / 0.001f;
            float Z = 0.f;
            for (int k = lane; k < 1024; k += 32)
                Z += expf(frow[k] / 0.001f - xm);
#pragma unroll
            for (int o = 16; o > 0; o >>= 1)
                Z += __shfl_xor_sync(0xffffffffu, Z, o);
            float m2 = -FLT_MAX;
            for (int k = lane; k < 1024; k += 32)
                if (expf(frow[k] / 0.001f - xm) / Z >= 0.019f)
                    m2 = fmaxf(m2, frow[k]);
#pragma unroll
            for (int o = 16; o > 0; o >>= 1)
                m2 = fmaxf(m2, __shfl_xor_sync(0xffffffffu, m2, o));
            const bool any = (m2 > -1e37f);
            float wsum = 0.f;
            if (any) {
                for (int k = lane; k < 1024; k += 32) {
                    float att = expf(frow[k] / 0.001f - xm) / Z;
                    if (att >= 0.019f) wsum += expf(frow[k] - m2);
                }
#pragma unroll
                for (int o = 16; o > 0; o >>= 1)
                    wsum += __shfl_xor_sync(0xffffffffu, wsum, o);
            }
            for (int k = 0; k < 1024; k++) {
                float wgt;
                if (!any) wgt = 1.f / 1024.f;
                else {
                    float att = expf(frow[k] / 0.001f - xm) / Z;
                    wgt = (att >= 0.019f) ? expf(frow[k] - m2) / wsum : 0.f;
                }
                a0 += wgt * vb[(size_t)k * HD + lane];
                a1 += wgt * vb[(size_t)k * HD + lane + 32];
            }
        }

        const int b_ = bh >> 4, h_ = bh & 15;
        float* dst = attn + ((size_t)(b_ * SDIM + q)) * DDIM + h_ * HD;
        dst[lane] = a0;
        dst[lane + 32] = a1;
    }
}

// ---------------------------------------------------------------------------
// bf16 3-product GEMM (O projection) — R7/R11 PROVEN VERSION, FROZEN.
// ---------------------------------------------------------------------------
__global__ __launch_bounds__(256, 1)
void mma_gemm_bf16(const float* __restrict__ A, int lda,
                   const float* __restrict__ B, int ldb,
                   const float* __restrict__ bias,
                   float* __restrict__ C, int head_layout)
{
    extern __shared__ __align__(16) uint32_t smu[];

    const int tid = threadIdx.x;
    const int w = tid >> 5;
    const int lane = tid & 31;
    const int g = lane >> 2;
    const int t = lane & 3;
    const int m0 = (w & 1) << 6;
    const int n0 = (w >> 1) << 5;
    const int row0 = blockIdx.y << 7;
    const int col0 = blockIdx.x << 7;

    float d[4][4][4];
#pragma unroll
    for (int i = 0; i < 4; i++)
#pragma unroll
        for (int j = 0; j < 4; j++)
#pragma unroll
            for (int e = 0; e < 4; e++) d[i][j][e] = 0.f;

    const int s_ = tid & 7;
    const int j0 = (2 * s_) & 7;
    const int phys0 = ((s_ >> 2) << 3) + ((j0 & 3) << 1) + (j0 >> 2);

    float4 pa[4], pb[4];
#pragma unroll
    for (int i = 0; i < 4; i++) {
        int idx = i * 256 + tid;
        int r = idx >> 3;
        pa[i] = *(const float4*)(A + (size_t)(row0 + r) * lda + s_ * 4);
        pb[i] = *(const float4*)(B + (size_t)(col0 + r) * ldb + s_ * 4);
    }

    for (int ch = 0; ch < 32; ch++) {
        const int sb = ch & 1;
        uint32_t* Ah  = smu + sb * 4 * BPLANE;
        uint32_t* Al  = Ah + BPLANE;
        uint32_t* Bh_ = Ah + 2 * BPLANE;
        uint32_t* Bl  = Ah + 3 * BPLANE;

#pragma unroll
        for (int i = 0; i < 4; i++) {
            int idx = i * 256 + tid;
            int r = idx >> 3;
            int wo = r * BPLD + phys0;
            float4 va = pa[i];
            float hx = __bfloat162float(__float2bfloat16_rn(va.x));
            float hy = __bfloat162float(__float2bfloat16_rn(va.y));
            float hz = __bfloat162float(__float2bfloat16_rn(va.z));
            float hw = __bfloat162float(__float2bfloat16_rn(va.w));
            Ah[wo]     = pack_bf16(hx, hy);
            Ah[wo + 2] = pack_bf16(hz, hw);
            Al[wo]     = pack_bf16(va.x - hx, va.y - hy);
            Al[wo + 2] = pack_bf16(va.z - hz, va.w - hw);
            float4 vbv = pb[i];
            hx = __bfloat162float(__float2bfloat16_rn(vbv.x));
            hy = __bfloat162float(__float2bfloat16_rn(vbv.y));
            hz = __bfloat162float(__float2bfloat16_rn(vbv.z));
            hw = __bfloat162float(__float2bfloat16_rn(vbv.w));
            Bh_[wo]     = pack_bf16(hx, hy);
            Bh_[wo + 2] = pack_bf16(hz, hw);
            Bl[wo]     = pack_bf16(vbv.x - hx, vbv.y - hy);
            Bl[wo + 2] = pack_bf16(vbv.z - hz, vbv.w - hw);
        }
        __syncthreads();

        if (ch < 31) {
            const int kc = (ch + 1) << 5;
#pragma unroll
            for (int i = 0; i < 4; i++) {
                int idx = i * 256 + tid;
                int r = idx >> 3;
                pa[i] = *(const float4*)(A + (size_t)(row0 + r) * lda + kc + s_ * 4);
                pb[i] = *(const float4*)(B + (size_t)(col0 + r) * ldb + kc + s_ * 4);
            }
        }

#pragma unroll
        for (int ks = 0; ks < 2; ks++) {
            const int kw = (ks << 3) + (t << 1);
            uint2 aH[4][2], aL[4][2], bH[4], bL[4];
#pragma unroll
            for (int mt = 0; mt < 4; mt++) {
                int rw = (m0 + (mt << 4) + g) * BPLD + kw;
                aH[mt][0] = *(const uint2*)&Ah[rw];
                aH[mt][1] = *(const uint2*)&Ah[rw + 8 * BPLD];
                aL[mt][0] = *(const uint2*)&Al[rw];
                aL[mt][1] = *(const uint2*)&Al[rw + 8 * BPLD];
            }
#pragma unroll
            for (int nt = 0; nt < 4; nt++) {
                int rw = (n0 + (nt << 3) + g) * BPLD + kw;
                bH[nt] = *(const uint2*)&Bh_[rw];
                bL[nt] = *(const uint2*)&Bl[rw];
            }
#pragma unroll
            for (int mt = 0; mt < 4; mt++)
#pragma unroll
                for (int nt = 0; nt < 4; nt++) {
                    MMA_BF16(d[mt][nt], aH[mt][0].x, aH[mt][1].x, aH[mt][0].y, aH[mt][1].y,
                             bH[nt].x, bH[nt].y);
                    MMA_BF16(d[mt][nt], aH[mt][0].x, aH[mt][1].x, aH[mt][0].y, aH[mt][1].y,
                             bL[nt].x, bL[nt].y);
                    MMA_BF16(d[mt][nt], aL[mt][0].x, aL[mt][1].x, aL[mt][0].y, aL[mt][1].y,
                             bH[nt].x, bH[nt].y);
                }
        }
    }

#pragma unroll
    for (int mt = 0; mt < 4; mt++) {
#pragma unroll
        for (int nt = 0; nt < 4; nt++) {
            int c = col0 + n0 + (nt << 3) + (t << 1);
            float b0 = bias[c];
            float b1 = bias[c + 1];
#pragma unroll
            for (int half = 0; half < 2; half++) {
                int r = row0 + m0 + (mt << 4) + g + half * 8;
                float2 v;
                v.x = d[mt][nt][half * 2 + 0] + b0;
                v.y = d[mt][nt][half * 2 + 1] + b1;
                if (head_layout) {
                    int b_ = r >> 10, s2 = r & 1023;
                    int h_ = c >> 6, d_ = c & 63;
                    *(float2*)(C + (((size_t)(b_ * NH + h_) * SDIM + s2) << 6) + d_) = v;
                } else {
                    *(float2*)(C + (size_t)r * 1024 + c) = v;
                }
            }
        }
    }
}

// ---------------------------------------------------------------------------
// 4x 1024x1024 transpose in one launch (z selects pair)
// ---------------------------------------------------------------------------
__global__ __launch_bounds__(256)
void transpose4_kernel(const float* __restrict__ i0, float* __restrict__ o0,
                       const float* __restrict__ i1, float* __restrict__ o1,
                       const float* __restrict__ i2, float* __restrict__ o2,
                       const float* __restrict__ i3, float* __restrict__ o3)
{
    __shared__ float tb[32][33];
    const float* in = (blockIdx.z == 0) ? i0 : (blockIdx.z == 1) ? i1
                    : (blockIdx.z == 2) ? i2 : i3;
    float* out      = (blockIdx.z == 0) ? o0 : (blockIdx.z == 1) ? o1
                    : (blockIdx.z == 2) ? o2 : o3;
    const int tx = threadIdx.x, ty = threadIdx.y;
    const int bx = blockIdx.x << 5, by = blockIdx.y << 5;
#pragma unroll
    for (int i = 0; i < 4; i++)
        tb[ty + i * 8][tx] = in[(size_t)(by + ty + i * 8) * 1024 + bx + tx];
    __syncthreads();
#pragma unroll
    for (int i = 0; i < 4; i++)
        out[(size_t)(bx + ty + i * 8) * 1024 + by + tx] = tb[tx][ty + i * 8];
}

// ---------------------------------------------------------------------------
extern "C" void kernel_launch(void* const* d_in, const int* in_sizes, int n_in,
                              void* d_out, int out_size)
{
    const float* Q  = (const float*)d_in[0];
    const float* K  = (const float*)d_in[1];
    const float* V  = (const float*)d_in[2];
    const float* Wq = (const float*)d_in[3];
    const float* bq = (const float*)d_in[4];
    const float* Wk = (const float*)d_in[5];
    const float* bk = (const float*)d_in[6];
    const float* Wv = (const float*)d_in[7];
    const float* bv = (const float*)d_in[8];
    const float* Wo = (const float*)d_in[9];
    const float* bo = (const float*)d_in[10];

    float *qh, *kh, *vh, *attn, *wqT, *wkT, *wvT, *woT;
    uint32_t *Qhi, *Qlo, *Khi, *Klo, *Vhi, *Vlo;
    uint32_t *wqhi, *wqlo, *wkhi, *wklo, *wvhi, *wvlo;
    cudaGetSymbolAddress((void**)&qh,   g_qh);
    cudaGetSymbolAddress((void**)&kh,   g_kh);
    cudaGetSymbolAddress((void**)&vh,   g_vh);
    cudaGetSymbolAddress((void**)&attn, g_attn);
    cudaGetSymbolAddress((void**)&wqT,  g_wqT);
    cudaGetSymbolAddress((void**)&wkT,  g_wkT);
    cudaGetSymbolAddress((void**)&wvT,  g_wvT);
    cudaGetSymbolAddress((void**)&woT,  g_woT);
    cudaGetSymbolAddress((void**)&Qhi,  g_Qhi);
    cudaGetSymbolAddress((void**)&Qlo,  g_Qlo);
    cudaGetSymbolAddress((void**)&Khi,  g_Khi);
    cudaGetSymbolAddress((void**)&Klo,  g_Klo);
    cudaGetSymbolAddress((void**)&Vhi,  g_Vhi);
    cudaGetSymbolAddress((void**)&Vlo,  g_Vlo);
    cudaGetSymbolAddress((void**)&wqhi, g_wqhi);
    cudaGetSymbolAddress((void**)&wqlo, g_wqlo);
    cudaGetSymbolAddress((void**)&wkhi, g_wkhi);
    cudaGetSymbolAddress((void**)&wklo, g_wklo);
    cudaGetSymbolAddress((void**)&wvhi, g_wvhi);
    cudaGetSymbolAddress((void**)&wvlo, g_wvlo);

    cudaFuncSetAttribute(mma_gemm_f16pre, cudaFuncAttributeMaxDynamicSharedMemorySize, GB_SMEM);
    cudaFuncSetAttribute(mma_gemm_bf16, cudaFuncAttributeMaxDynamicSharedMemorySize, GB_SMEM);
    cudaFuncSetAttribute(fused_scores_mask,
                         cudaFuncAttributeMaxDynamicSharedMemorySize, F_SMEM);

    // weight transposes
    transpose4_kernel<<<dim3(32, 32, 4), dim3(32, 8)>>>(Wq, wqT, Wk, wkT,
                                                        Wv, wvT, Wo, woT);

    // pre-split Q,K,V + wqT,wkT,wvT into fp16 hi/lo (permuted layout)
    split6_kernel<<<dim3(32, 6), 256>>>(Q, Qhi, Qlo, K, Khi, Klo, V, Vhi, Vlo,
                                        wqT, wqhi, wqlo, wkT, wkhi, wklo,
                                        wvT, wvhi, wvlo);

    // Q,K,V projections in ONE launch: fp16-3, conversion-free staging
    mma_gemm_f16pre<<<dim3(8, 32, 3), 256, GB_SMEM>>>(
        Qhi, Qlo, wqhi, wqlo,
        Khi, Klo, wkhi, wklo,
        Vhi, Vlo, wvhi, wvlo,
        bq, bk, bv, qh, kh, vh);

    // fused scores + mask + sparse AV (frozen R15 version)
    fused_scores_mask<<<dim3(8, NBH), 256, F_SMEM>>>(qh, kh, vh, attn);

    // output projection: pipelined bf16-3 (frozen)
    mma_gemm_bf16<<<dim3(8, 32), 256, GB_SMEM>>>(attn, 1024, woT, 1024, bo,
                                                 (float*)d_out, 0);
}

// round 17
// speedup vs baseline: 1.1020x; 1.1020x over previous
#include <cuda_runtime.h>
#include <cuda_bf16.h>
#include <cuda_fp16.h>
#include <math.h>
#include <stdint.h>
#include <float.h>

#define SDIM 1024
#define DDIM 1024
#define NH 16
#define HD 64
#define NBH 64
#define MTOT 4096

// ---------------- scratch (__device__ globals; no runtime alloc) ------------
__device__ float g_qh[NBH * SDIM * HD];
__device__ float g_kh[NBH * SDIM * HD];
__device__ float g_vh[NBH * SDIM * HD];
__device__ float g_attn[(size_t)MTOT * DDIM];
__device__ float g_wqT[DDIM * DDIM];
__device__ float g_wkT[DDIM * DDIM];
__device__ float g_wvT[DDIM * DDIM];
__device__ float g_woT[DDIM * DDIM];

// ---------------- helpers ----------------------------------------------------
#define MMA_BF16(d, a0, a1, a2, a3, b0, b1) \
    asm volatile("mma.sync.aligned.m16n8k16.row.col.f32.bf16.bf16.f32 " \
                 "{%0,%1,%2,%3}, {%4,%5,%6,%7}, {%8,%9}, {%0,%1,%2,%3};" \
                 : "+f"((d)[0]), "+f"((d)[1]), "+f"((d)[2]), "+f"((d)[3]) \
                 : "r"(a0), "r"(a1), "r"(a2), "r"(a3), "r"(b0), "r"(b1))

#define MMA_F16(d, a0, a1, a2, a3, b0, b1) \
    asm volatile("mma.sync.aligned.m16n8k16.row.col.f32.f16.f16.f32 " \
                 "{%0,%1,%2,%3}, {%4,%5,%6,%7}, {%8,%9}, {%0,%1,%2,%3};" \
                 : "+f"((d)[0]), "+f"((d)[1]), "+f"((d)[2]), "+f"((d)[3]) \
                 : "r"(a0), "r"(a1), "r"(a2), "r"(a3), "r"(b0), "r"(b1))

// monotone float<->uint encoding for atomicMax on floats
__device__ __forceinline__ unsigned fenc(float f) {
    unsigned u = __float_as_uint(f);
    return (u & 0x80000000u) ? ~u : (u | 0x80000000u);
}
__device__ __forceinline__ float fdec(unsigned u) {
    unsigned v = (u & 0x80000000u) ? (u & 0x7FFFFFFFu) : ~u;
    return __uint_as_float(v);
}
__device__ __forceinline__ uint32_t pack_half(float a, float b) {
    __half2 v = __floats2half2_rn(a, b);
    return *reinterpret_cast<uint32_t*>(&v);
}
__device__ __forceinline__ uint32_t pack_bf16(float a, float b) {
    __nv_bfloat162 v = __floats2bfloat162_rn(a, b);
    return *reinterpret_cast<uint32_t*>(&v);
}

// ---------------------------------------------------------------------------
// FUSED scores + mask + sparse AV — R15 PROVEN VERSION, FROZEN.
// ---------------------------------------------------------------------------
#define QLD 36
#define CAP 32
#define F_SMEM (18432 + 18432 + 512 + 512 + 16384 + 16384)   // 70656 B

__global__ __launch_bounds__(256, 2)
void fused_scores_mask(const float* __restrict__ qh, const float* __restrict__ kh,
                       const float* __restrict__ vh, float* __restrict__ attn)
{
    extern __shared__ __align__(16) char fsm[];
    uint32_t* Ap      = (uint32_t*)fsm;
    uint32_t* Bp      = (uint32_t*)(fsm + 18432);
    unsigned* rowmaxU = (unsigned*)(fsm + 36864);
    int*      cntI    = (int*)(fsm + 37376);
    int*      listKs  = (int*)(fsm + 37888);
    float*    listSs  = (float*)(fsm + 54272);

    const int tid = threadIdx.x;
    const int w = tid >> 5;
    const int lane = tid & 31;
    const int g = lane >> 2;
    const int t = lane & 3;
    const int m0 = (w & 1) << 6;
    const int n0 = (w >> 1) << 5;
    const int bh = blockIdx.y;
    const int q0 = blockIdx.x << 7;

    const float* qbase = qh + ((size_t)bh * SDIM + q0) * HD;
    const float* kbh   = kh + (size_t)bh * SDIM * HD;
    const float* vb    = vh + (size_t)bh * SDIM * HD;

    if (tid < 128) { rowmaxU[tid] = 0u; cntI[tid] = 0; }

#pragma unroll
    for (int i = 0; i < 8; i++) {
        int idx = i * 256 + tid;
        int r = idx >> 4, s16 = idx & 15;
        float4 v = *(const float4*)(qbase + (size_t)r * HD + s16 * 4);
        int j0 = (2 * s16) & 7;
        int wo = r * QLD + ((s16 >> 2) << 3) + ((j0 & 3) << 1) + (j0 >> 2);
        Ap[wo]     = pack_half(v.x, v.y);
        Ap[wo + 2] = pack_half(v.z, v.w);
    }

    for (int ch = 0; ch < 8; ch++) {
        __syncthreads();
#pragma unroll
        for (int i = 0; i < 8; i++) {
            int idx = i * 256 + tid;
            int r = idx >> 4, s16 = idx & 15;
            float4 v = *(const float4*)(kbh + (size_t)(ch * 128 + r) * HD + s16 * 4);
            int j0 = (2 * s16) & 7;
            int wo = r * QLD + ((s16 >> 2) << 3) + ((j0 & 3) << 1) + (j0 >> 2);
            Bp[wo]     = pack_half(v.x, v.y);
            Bp[wo + 2] = pack_half(v.z, v.w);
        }
        __syncthreads();

        float d[4][4][4];
#pragma unroll
        for (int i = 0; i < 4; i++)
#pragma unroll
            for (int j = 0; j < 4; j++)
#pragma unroll
                for (int e = 0; e < 4; e++) d[i][j][e] = 0.f;

#pragma unroll
        for (int ks = 0; ks < 4; ks++) {
            const int kw = (ks << 3) + (t << 1);
            uint2 aF[4][2], bF[4];
#pragma unroll
            for (int mt = 0; mt < 4; mt++) {
                int rw = (m0 + (mt << 4) + g) * QLD + kw;
                aF[mt][0] = *(const uint2*)&Ap[rw];
                aF[mt][1] = *(const uint2*)&Ap[rw + 8 * QLD];
            }
#pragma unroll
            for (int nt = 0; nt < 4; nt++) {
                int rw = (n0 + (nt << 3) + g) * QLD + kw;
                bF[nt] = *(const uint2*)&Bp[rw];
            }
#pragma unroll
            for (int mt = 0; mt < 4; mt++)
#pragma unroll
                for (int nt = 0; nt < 4; nt++)
                    MMA_F16(d[mt][nt], aF[mt][0].x, aF[mt][1].x,
                            aF[mt][0].y, aF[mt][1].y, bF[nt].x, bF[nt].y);
        }

#pragma unroll
        for (int mt = 0; mt < 4; mt++)
#pragma unroll
            for (int half = 0; half < 2; half++) {
                float mx = -FLT_MAX;
#pragma unroll
                for (int nt = 0; nt < 4; nt++)
                    mx = fmaxf(mx, fmaxf(d[mt][nt][half * 2],
                                         d[mt][nt][half * 2 + 1]));
                mx = fmaxf(mx, __shfl_xor_sync(0xffffffffu, mx, 1));
                mx = fmaxf(mx, __shfl_xor_sync(0xffffffffu, mx, 2));
                if (t == 0)
                    atomicMax(&rowmaxU[m0 + (mt << 4) + g + half * 8], fenc(mx));
            }
        __syncthreads();

#pragma unroll
        for (int mt = 0; mt < 4; mt++)
#pragma unroll
            for (int half = 0; half < 2; half++) {
                const int row = m0 + (mt << 4) + g + half * 8;
                const float band = fdec(rowmaxU[row]) - 0.32f;
#pragma unroll
                for (int nt = 0; nt < 4; nt++)
#pragma unroll
                    for (int e = 0; e < 2; e++) {
                        float v = d[mt][nt][half * 2 + e];
                        if (v >= band) {
                            int pos = atomicAdd(&cntI[row], 1);
                            if (pos < CAP) {
                                listKs[row * CAP + pos] =
                                    ch * 128 + n0 + (nt << 3) + (t << 1) + e;
                                listSs[row * CAP + pos] = v;
                            }
                        }
                    }
            }
    }
    __syncthreads();

    float* fb = (float*)fsm;

    for (int rr = 0; rr < 16; rr++) {
        const int r = w * 16 + rr;
        const int q = q0 + r;
        const float* qrow = qbase + (size_t)r * HD;
        int cnt = cntI[r];
        float a0 = 0.f, a1 = 0.f;

        if (cnt <= CAP) {
            if (lane == 0) {
                const float bandf = fdec(rowmaxU[r]) - 0.32f;
                int nc = 0;
                for (int j = 0; j < cnt; j++) {
                    if (listSs[r * CAP + j] >= bandf)
                        listKs[r * CAP + nc++] = listKs[r * CAP + j];
                }
                for (int a = 1; a < nc; a++) {
                    int key = listKs[r * CAP + a];
                    int b = a - 1;
                    while (b >= 0 && listKs[r * CAP + b] > key) {
                        listKs[r * CAP + b + 1] = listKs[r * CAP + b];
                        b--;
                    }
                    listKs[r * CAP + b + 1] = key;
                }
                cntI[r] = nc;
            }
            __syncwarp();
            cnt = cntI[r];

            const float qa = qrow[lane], qb = qrow[lane + 32];
            for (int j = 0; j < cnt; j++) {
                const int k = listKs[r * CAP + j];
                const float* krow = kbh + (size_t)k * HD;
                float p = qa * krow[lane] + qb * krow[lane + 32];
#pragma unroll
                for (int o = 16; o > 0; o >>= 1)
                    p += __shfl_xor_sync(0xffffffffu, p, o);
                if (lane == 0) listSs[r * CAP + j] = p * 0.125f;
            }
            __syncwarp();

            float m_ex = -FLT_MAX;
            for (int j = 0; j < cnt; j++) m_ex = fmaxf(m_ex, listSs[r * CAP + j]);
            const float xm = m_ex / 0.001f;
            float Z = 0.f;
            for (int j = 0; j < cnt; j++)
                Z += expf(listSs[r * CAP + j] / 0.001f - xm);

            float m2 = -FLT_MAX;
            for (int j = 0; j < cnt; j++) {
                float att = expf(listSs[r * CAP + j] / 0.001f - xm) / Z;
                if (att >= 0.019f) m2 = fmaxf(m2, listSs[r * CAP + j]);
            }
            float wsum = 0.f;
            for (int j = 0; j < cnt; j++) {
                float s = listSs[r * CAP + j];
                float att = expf(s / 0.001f - xm) / Z;
                if (att >= 0.019f) wsum += expf(s - m2);
            }
            for (int j = 0; j < cnt; j++) {
                float s = listSs[r * CAP + j];
                float att = expf(s / 0.001f - xm) / Z;
                if (att >= 0.019f) {
                    float wgt = expf(s - m2) / wsum;
                    const int k = listKs[r * CAP + j];
                    a0 += wgt * vb[(size_t)k * HD + lane];
                    a1 += wgt * vb[(size_t)k * HD + lane + 32];
                }
            }
        } else {
            float* frow = fb + w * 1024;
            for (int it = 0; it < 32; it++) {
                int k = it * 32 + lane;
                const float* krow = kbh + (size_t)k * HD;
                float p = 0.f;
#pragma unroll
                for (int dd = 0; dd < 64; dd++) p += qrow[dd] * krow[dd];
                frow[k] = p * 0.125f;
            }
            __syncwarp();
            float me = -FLT_MAX;
            for (int k = lane; k < 1024; k += 32) me = fmaxf(me, frow[k]);
#pragma unroll
            for (int o = 16; o > 0; o >>= 1)
                me = fmaxf(me, __shfl_xor_sync(0xffffffffu, me, o));
            const float xm = me / 0.001f;
            float Z = 0.f;
            for (int k = lane; k < 1024; k += 32)
                Z += expf(frow[k] / 0.001f - xm);
#pragma unroll
            for (int o = 16; o > 0; o >>= 1)
                Z += __shfl_xor_sync(0xffffffffu, Z, o);
            float m2 = -FLT_MAX;
            for (int k = lane; k < 1024; k += 32)
                if (expf(frow[k] / 0.001f - xm) / Z >= 0.019f)
                    m2 = fmaxf(m2, frow[k]);
#pragma unroll
            for (int o = 16; o > 0; o >>= 1)
                m2 = fmaxf(m2, __shfl_xor_sync(0xffffffffu, m2, o));
            const bool any = (m2 > -1e37f);
            float wsum = 0.f;
            if (any) {
                for (int k = lane; k < 1024; k += 32) {
                    float att = expf(frow[k] / 0.001f - xm) / Z;
                    if (att >= 0.019f) wsum += expf(frow[k] - m2);
                }
#pragma unroll
                for (int o = 16; o > 0; o >>= 1)
                    wsum += __shfl_xor_sync(0xffffffffu, wsum, o);
            }
            for (int k = 0; k < 1024; k++) {
                float wgt;
                if (!any) wgt = 1.f / 1024.f;
                else {
                    float att = expf(frow[k] / 0.001f - xm) / Z;
                    wgt = (att >= 0.019f) ? expf(frow[k] - m2) / wsum : 0.f;
                }
                a0 += wgt * vb[(size_t)k * HD + lane];
                a1 += wgt * vb[(size_t)k * HD + lane + 32];
            }
        }

        const int b_ = bh >> 4, h_ = bh & 15;
        float* dst = attn + ((size_t)(b_ * SDIM + q)) * DDIM + h_ * HD;
        dst[lane] = a0;
        dst[lane + 32] = a1;
    }
}

// ---------------------------------------------------------------------------
// fp16 3-product GEMM for Q, K & V projections (z selects, z=3) —
// R13-proven kernel body; only the operand-select ternary extended.
// head_layout output for all three.
// ---------------------------------------------------------------------------
#define BPLD 20
#define BPLANE (128 * BPLD)
#define GB_SMEM (2 * 4 * BPLANE * 4)   // 81920 B

__global__ __launch_bounds__(256, 1)
void mma_gemm_f16qkv(const float* __restrict__ A0, const float* __restrict__ W0,
                     const float* __restrict__ b0, float* __restrict__ C0,
                     const float* __restrict__ A1, const float* __restrict__ W1,
                     const float* __restrict__ b1, float* __restrict__ C1,
                     const float* __restrict__ A2, const float* __restrict__ W2,
                     const float* __restrict__ b2, float* __restrict__ C2)
{
    extern __shared__ __align__(16) uint32_t smu[];

    const int z = blockIdx.z;
    const float* A    = (z == 0) ? A0 : (z == 1) ? A1 : A2;
    const float* B    = (z == 0) ? W0 : (z == 1) ? W1 : W2;
    const float* bias = (z == 0) ? b0 : (z == 1) ? b1 : b2;
    float* C          = (z == 0) ? C0 : (z == 1) ? C1 : C2;

    const int tid = threadIdx.x;
    const int w = tid >> 5;
    const int lane = tid & 31;
    const int g = lane >> 2;
    const int t = lane & 3;
    const int m0 = (w & 1) << 6;
    const int n0 = (w >> 1) << 5;
    const int row0 = blockIdx.y << 7;
    const int col0 = blockIdx.x << 7;

    float d[4][4][4];
#pragma unroll
    for (int i = 0; i < 4; i++)
#pragma unroll
        for (int j = 0; j < 4; j++)
#pragma unroll
            for (int e = 0; e < 4; e++) d[i][j][e] = 0.f;

    const int s_ = tid & 7;
    const int j0 = (2 * s_) & 7;
    const int phys0 = ((s_ >> 2) << 3) + ((j0 & 3) << 1) + (j0 >> 2);

    float4 pa[4], pb[4];
#pragma unroll
    for (int i = 0; i < 4; i++) {
        int idx = i * 256 + tid;
        int r = idx >> 3;
        pa[i] = *(const float4*)(A + (size_t)(row0 + r) * 1024 + s_ * 4);
        pb[i] = *(const float4*)(B + (size_t)(col0 + r) * 1024 + s_ * 4);
    }

    for (int ch = 0; ch < 32; ch++) {
        const int sb = ch & 1;
        uint32_t* Ah  = smu + sb * 4 * BPLANE;
        uint32_t* Al  = Ah + BPLANE;
        uint32_t* Bh_ = Ah + 2 * BPLANE;
        uint32_t* Bl  = Ah + 3 * BPLANE;

#pragma unroll
        for (int i = 0; i < 4; i++) {
            int idx = i * 256 + tid;
            int r = idx >> 3;
            int wo = r * BPLD + phys0;
            float4 va = pa[i];
            float hx = __half2float(__float2half_rn(va.x));
            float hy = __half2float(__float2half_rn(va.y));
            float hz = __half2float(__float2half_rn(va.z));
            float hw = __half2float(__float2half_rn(va.w));
            Ah[wo]     = pack_half(hx, hy);
            Ah[wo + 2] = pack_half(hz, hw);
            Al[wo]     = pack_half(va.x - hx, va.y - hy);
            Al[wo + 2] = pack_half(va.z - hz, va.w - hw);
            float4 vbv = pb[i];
            hx = __half2float(__float2half_rn(vbv.x));
            hy = __half2float(__float2half_rn(vbv.y));
            hz = __half2float(__float2half_rn(vbv.z));
            hw = __half2float(__float2half_rn(vbv.w));
            Bh_[wo]     = pack_half(hx, hy);
            Bh_[wo + 2] = pack_half(hz, hw);
            Bl[wo]     = pack_half(vbv.x - hx, vbv.y - hy);
            Bl[wo + 2] = pack_half(vbv.z - hz, vbv.w - hw);
        }
        __syncthreads();

        if (ch < 31) {
            const int kc = (ch + 1) << 5;
#pragma unroll
            for (int i = 0; i < 4; i++) {
                int idx = i * 256 + tid;
                int r = idx >> 3;
                pa[i] = *(const float4*)(A + (size_t)(row0 + r) * 1024 + kc + s_ * 4);
                pb[i] = *(const float4*)(B + (size_t)(col0 + r) * 1024 + kc + s_ * 4);
            }
        }

#pragma unroll
        for (int ks = 0; ks < 2; ks++) {
            const int kw = (ks << 3) + (t << 1);
            uint2 aH[4][2], aL[4][2], bH[4], bL[4];
#pragma unroll
            for (int mt = 0; mt < 4; mt++) {
                int rw = (m0 + (mt << 4) + g) * BPLD + kw;
                aH[mt][0] = *(const uint2*)&Ah[rw];
                aH[mt][1] = *(const uint2*)&Ah[rw + 8 * BPLD];
                aL[mt][0] = *(const uint2*)&Al[rw];
                aL[mt][1] = *(const uint2*)&Al[rw + 8 * BPLD];
            }
#pragma unroll
            for (int nt = 0; nt < 4; nt++) {
                int rw = (n0 + (nt << 3) + g) * BPLD + kw;
                bH[nt] = *(const uint2*)&Bh_[rw];
                bL[nt] = *(const uint2*)&Bl[rw];
            }
#pragma unroll
            for (int mt = 0; mt < 4; mt++)
#pragma unroll
                for (int nt = 0; nt < 4; nt++) {
                    MMA_F16(d[mt][nt], aH[mt][0].x, aH[mt][1].x, aH[mt][0].y, aH[mt][1].y,
                            bH[nt].x, bH[nt].y);
                    MMA_F16(d[mt][nt], aH[mt][0].x, aH[mt][1].x, aH[mt][0].y, aH[mt][1].y,
                            bL[nt].x, bL[nt].y);
                    MMA_F16(d[mt][nt], aL[mt][0].x, aL[mt][1].x, aL[mt][0].y, aL[mt][1].y,
                            bH[nt].x, bH[nt].y);
                }
        }
    }

#pragma unroll
    for (int mt = 0; mt < 4; mt++) {
#pragma unroll
        for (int nt = 0; nt < 4; nt++) {
            int c = col0 + n0 + (nt << 3) + (t << 1);
            float b0v = bias[c];
            float b1v = bias[c + 1];
#pragma unroll
            for (int half = 0; half < 2; half++) {
                int r = row0 + m0 + (mt << 4) + g + half * 8;
                float2 v;
                v.x = d[mt][nt][half * 2 + 0] + b0v;
                v.y = d[mt][nt][half * 2 + 1] + b1v;
                int b_ = r >> 10, s2 = r & 1023;
                int h_ = c >> 6, d_ = c & 63;
                *(float2*)(C + (((size_t)(b_ * NH + h_) * SDIM + s2) << 6) + d_) = v;
            }
        }
    }
}

// ---------------------------------------------------------------------------
// bf16 3-product GEMM (O projection) — R7/R11 PROVEN VERSION, FROZEN.
// ---------------------------------------------------------------------------
__global__ __launch_bounds__(256, 1)
void mma_gemm_bf16(const float* __restrict__ A, int lda,
                   const float* __restrict__ B, int ldb,
                   const float* __restrict__ bias,
                   float* __restrict__ C, int head_layout)
{
    extern __shared__ __align__(16) uint32_t smu[];

    const int tid = threadIdx.x;
    const int w = tid >> 5;
    const int lane = tid & 31;
    const int g = lane >> 2;
    const int t = lane & 3;
    const int m0 = (w & 1) << 6;
    const int n0 = (w >> 1) << 5;
    const int row0 = blockIdx.y << 7;
    const int col0 = blockIdx.x << 7;

    float d[4][4][4];
#pragma unroll
    for (int i = 0; i < 4; i++)
#pragma unroll
        for (int j = 0; j < 4; j++)
#pragma unroll
            for (int e = 0; e < 4; e++) d[i][j][e] = 0.f;

    const int s_ = tid & 7;
    const int j0 = (2 * s_) & 7;
    const int phys0 = ((s_ >> 2) << 3) + ((j0 & 3) << 1) + (j0 >> 2);

    float4 pa[4], pb[4];
#pragma unroll
    for (int i = 0; i < 4; i++) {
        int idx = i * 256 + tid;
        int r = idx >> 3;
        pa[i] = *(const float4*)(A + (size_t)(row0 + r) * lda + s_ * 4);
        pb[i] = *(const float4*)(B + (size_t)(col0 + r) * ldb + s_ * 4);
    }

    for (int ch = 0; ch < 32; ch++) {
        const int sb = ch & 1;
        uint32_t* Ah  = smu + sb * 4 * BPLANE;
        uint32_t* Al  = Ah + BPLANE;
        uint32_t* Bh_ = Ah + 2 * BPLANE;
        uint32_t* Bl  = Ah + 3 * BPLANE;

#pragma unroll
        for (int i = 0; i < 4; i++) {
            int idx = i * 256 + tid;
            int r = idx >> 3;
            int wo = r * BPLD + phys0;
            float4 va = pa[i];
            float hx = __bfloat162float(__float2bfloat16_rn(va.x));
            float hy = __bfloat162float(__float2bfloat16_rn(va.y));
            float hz = __bfloat162float(__float2bfloat16_rn(va.z));
            float hw = __bfloat162float(__float2bfloat16_rn(va.w));
            Ah[wo]     = pack_bf16(hx, hy);
            Ah[wo + 2] = pack_bf16(hz, hw);
            Al[wo]     = pack_bf16(va.x - hx, va.y - hy);
            Al[wo + 2] = pack_bf16(va.z - hz, va.w - hw);
            float4 vbv = pb[i];
            hx = __bfloat162float(__float2bfloat16_rn(vbv.x));
            hy = __bfloat162float(__float2bfloat16_rn(vbv.y));
            hz = __bfloat162float(__float2bfloat16_rn(vbv.z));
            hw = __bfloat162float(__float2bfloat16_rn(vbv.w));
            Bh_[wo]     = pack_bf16(hx, hy);
            Bh_[wo + 2] = pack_bf16(hz, hw);
            Bl[wo]     = pack_bf16(vbv.x - hx, vbv.y - hy);
            Bl[wo + 2] = pack_bf16(vbv.z - hz, vbv.w - hw);
        }
        __syncthreads();

        if (ch < 31) {
            const int kc = (ch + 1) << 5;
#pragma unroll
            for (int i = 0; i < 4; i++) {
                int idx = i * 256 + tid;
                int r = idx >> 3;
                pa[i] = *(const float4*)(A + (size_t)(row0 + r) * lda + kc + s_ * 4);
                pb[i] = *(const float4*)(B + (size_t)(col0 + r) * ldb + kc + s_ * 4);
            }
        }

#pragma unroll
        for (int ks = 0; ks < 2; ks++) {
            const int kw = (ks << 3) + (t << 1);
            uint2 aH[4][2], aL[4][2], bH[4], bL[4];
#pragma unroll
            for (int mt = 0; mt < 4; mt++) {
                int rw = (m0 + (mt << 4) + g) * BPLD + kw;
                aH[mt][0] = *(const uint2*)&Ah[rw];
                aH[mt][1] = *(const uint2*)&Ah[rw + 8 * BPLD];
                aL[mt][0] = *(const uint2*)&Al[rw];
                aL[mt][1] = *(const uint2*)&Al[rw + 8 * BPLD];
            }
#pragma unroll
            for (int nt = 0; nt < 4; nt++) {
                int rw = (n0 + (nt << 3) + g) * BPLD + kw;
                bH[nt] = *(const uint2*)&Bh_[rw];
                bL[nt] = *(const uint2*)&Bl[rw];
            }
#pragma unroll
            for (int mt = 0; mt < 4; mt++)
#pragma unroll
                for (int nt = 0; nt < 4; nt++) {
                    MMA_BF16(d[mt][nt], aH[mt][0].x, aH[mt][1].x, aH[mt][0].y, aH[mt][1].y,
                             bH[nt].x, bH[nt].y);
                    MMA_BF16(d[mt][nt], aH[mt][0].x, aH[mt][1].x, aH[mt][0].y, aH[mt][1].y,
                             bL[nt].x, bL[nt].y);
                    MMA_BF16(d[mt][nt], aL[mt][0].x, aL[mt][1].x, aL[mt][0].y, aL[mt][1].y,
                             bH[nt].x, bH[nt].y);
                }
        }
    }

#pragma unroll
    for (int mt = 0; mt < 4; mt++) {
#pragma unroll
        for (int nt = 0; nt < 4; nt++) {
            int c = col0 + n0 + (nt << 3) + (t << 1);
            float b0 = bias[c];
            float b1 = bias[c + 1];
#pragma unroll
            for (int half = 0; half < 2; half++) {
                int r = row0 + m0 + (mt << 4) + g + half * 8;
                float2 v;
                v.x = d[mt][nt][half * 2 + 0] + b0;
                v.y = d[mt][nt][half * 2 + 1] + b1;
                if (head_layout) {
                    int b_ = r >> 10, s2 = r & 1023;
                    int h_ = c >> 6, d_ = c & 63;
                    *(float2*)(C + (((size_t)(b_ * NH + h_) * SDIM + s2) << 6) + d_) = v;
                } else {
                    *(float2*)(C + (size_t)r * 1024 + c) = v;
                }
            }
        }
    }
}

// ---------------------------------------------------------------------------
// 4x 1024x1024 transpose in one launch (z selects pair)
// ---------------------------------------------------------------------------
__global__ __launch_bounds__(256)
void transpose4_kernel(const float* __restrict__ i0, float* __restrict__ o0,
                       const float* __restrict__ i1, float* __restrict__ o1,
                       const float* __restrict__ i2, float* __restrict__ o2,
                       const float* __restrict__ i3, float* __restrict__ o3)
{
    __shared__ float tb[32][33];
    const float* in = (blockIdx.z == 0) ? i0 : (blockIdx.z == 1) ? i1
                    : (blockIdx.z == 2) ? i2 : i3;
    float* out      = (blockIdx.z == 0) ? o0 : (blockIdx.z == 1) ? o1
                    : (blockIdx.z == 2) ? o2 : o3;
    const int tx = threadIdx.x, ty = threadIdx.y;
    const int bx = blockIdx.x << 5, by = blockIdx.y << 5;
#pragma unroll
    for (int i = 0; i < 4; i++)
        tb[ty + i * 8][tx] = in[(size_t)(by + ty + i * 8) * 1024 + bx + tx];
    __syncthreads();
#pragma unroll
    for (int i = 0; i < 4; i++)
        out[(size_t)(bx + ty + i * 8) * 1024 + by + tx] = tb[tx][ty + i * 8];
}

// ---------------------------------------------------------------------------
extern "C" void kernel_launch(void* const* d_in, const int* in_sizes, int n_in,
                              void* d_out, int out_size)
{
    const float* Q  = (const float*)d_in[0];
    const float* K  = (const float*)d_in[1];
    const float* V  = (const float*)d_in[2];
    const float* Wq = (const float*)d_in[3];
    const float* bq = (const float*)d_in[4];
    const float* Wk = (const float*)d_in[5];
    const float* bk = (const float*)d_in[6];
    const float* Wv = (const float*)d_in[7];
    const float* bv = (const float*)d_in[8];
    const float* Wo = (const float*)d_in[9];
    const float* bo = (const float*)d_in[10];

    float *qh, *kh, *vh, *attn, *wqT, *wkT, *wvT, *woT;
    cudaGetSymbolAddress((void**)&qh,   g_qh);
    cudaGetSymbolAddress((void**)&kh,   g_kh);
    cudaGetSymbolAddress((void**)&vh,   g_vh);
    cudaGetSymbolAddress((void**)&attn, g_attn);
    cudaGetSymbolAddress((void**)&wqT,  g_wqT);
    cudaGetSymbolAddress((void**)&wkT,  g_wkT);
    cudaGetSymbolAddress((void**)&wvT,  g_wvT);
    cudaGetSymbolAddress((void**)&woT,  g_woT);

    cudaFuncSetAttribute(mma_gemm_f16qkv, cudaFuncAttributeMaxDynamicSharedMemorySize, GB_SMEM);
    cudaFuncSetAttribute(mma_gemm_bf16, cudaFuncAttributeMaxDynamicSharedMemorySize, GB_SMEM);
    cudaFuncSetAttribute(fused_scores_mask,
                         cudaFuncAttributeMaxDynamicSharedMemorySize, F_SMEM);

    // all 4 weight transposes in one launch
    transpose4_kernel<<<dim3(32, 32, 4), dim3(32, 8)>>>(Wq, wqT, Wk, wkT,
                                                        Wv, wvT, Wo, woT);

    // Q, K, V projections: ONE fp16-3 launch (z=3)
    mma_gemm_f16qkv<<<dim3(8, 32, 3), 256, GB_SMEM>>>(Q, wqT, bq, qh,
                                                      K, wkT, bk, kh,
                                                      V, wvT, bv, vh);

    // fused scores + mask + sparse AV (frozen R15 version)
    fused_scores_mask<<<dim3(8, NBH), 256, F_SMEM>>>(qh, kh, vh, attn);

    // output projection: pipelined bf16-3 (frozen)
    mma_gemm_bf16<<<dim3(8, 32), 256, GB_SMEM>>>(attn, 1024, woT, 1024, bo,
                                                 (float*)d_out, 0);
}